// round 1
// baseline (speedup 1.0000x reference)
#include <cuda_runtime.h>
#include <math.h>

#define N_COLS 4096
#define TPB    256
#define EPS    1e-14f

// scratch for the normalization scalar (no allocs allowed)
__device__ float g_s2;

// --- Step 1: s2 = (1/(||v|| + eps))^2, single block -------------------------
__global__ void norm_kernel(const float* __restrict__ v) {
    __shared__ float red[32];
    float sum = 0.0f;
    for (int i = threadIdx.x; i < N_COLS; i += blockDim.x) {
        float t = v[i];
        sum = fmaf(t, t, sum);
    }
    #pragma unroll
    for (int o = 16; o > 0; o >>= 1)
        sum += __shfl_xor_sync(0xffffffffu, sum, o);
    int w = threadIdx.x >> 5, l = threadIdx.x & 31;
    if (l == 0) red[w] = sum;
    __syncthreads();
    if (w == 0) {
        sum = (l < (blockDim.x >> 5)) ? red[l] : 0.0f;
        #pragma unroll
        for (int o = 16; o > 0; o >>= 1)
            sum += __shfl_xor_sync(0xffffffffu, sum, o);
        if (l == 0) {
            float s = 1.0f / (sqrtf(sum) + EPS);
            g_s2 = s * s;
        }
    }
}

// --- Step 2: one block per row, row read ONCE -------------------------------
// out[i] = x[i] - (2 * (x . v) * s2) * v[i] + bias[i]
__global__ void __launch_bounds__(TPB, 4)
householder_kernel(const float* __restrict__ x,
                   const float* __restrict__ v,
                   const float* __restrict__ bias,
                   float* __restrict__ out) {
    const int row = blockIdx.x;
    const float4* __restrict__ xr = (const float4*)(x + (size_t)row * N_COLS);
    const float4* __restrict__ vr = (const float4*)v;
    const float4* __restrict__ br = (const float4*)bias;
    float4* __restrict__       orow = (float4*)(out + (size_t)row * N_COLS);

    // 256 threads * 4 float4 = 4096 floats = one row, x and v held in regs.
    float4 xv[4], vv[4];
    float dot = 0.0f;
    #pragma unroll
    for (int j = 0; j < 4; j++) {
        int idx = threadIdx.x + j * TPB;   // coalesced 128B per warp
        xv[j] = xr[idx];
        vv[j] = vr[idx];
        dot = fmaf(xv[j].x, vv[j].x, dot);
        dot = fmaf(xv[j].y, vv[j].y, dot);
        dot = fmaf(xv[j].z, vv[j].z, dot);
        dot = fmaf(xv[j].w, vv[j].w, dot);
    }

    // block reduction of the row dot product
    #pragma unroll
    for (int o = 16; o > 0; o >>= 1)
        dot += __shfl_xor_sync(0xffffffffu, dot, o);

    __shared__ float red[TPB / 32];
    __shared__ float coef_sh;
    int w = threadIdx.x >> 5, l = threadIdx.x & 31;
    if (l == 0) red[w] = dot;
    __syncthreads();
    if (threadIdx.x == 0) {
        float t = 0.0f;
        #pragma unroll
        for (int i = 0; i < TPB / 32; i++) t += red[i];
        coef_sh = 2.0f * t * g_s2;
    }
    __syncthreads();
    const float coef = coef_sh;

    #pragma unroll
    for (int j = 0; j < 4; j++) {
        int idx = threadIdx.x + j * TPB;
        float4 bb = br[idx];
        float4 o4;
        o4.x = fmaf(-coef, vv[j].x, xv[j].x) + bb.x;
        o4.y = fmaf(-coef, vv[j].y, xv[j].y) + bb.y;
        o4.z = fmaf(-coef, vv[j].z, xv[j].z) + bb.z;
        o4.w = fmaf(-coef, vv[j].w, xv[j].w) + bb.w;
        orow[idx] = o4;
    }
}

extern "C" void kernel_launch(void* const* d_in, const int* in_sizes, int n_in,
                              void* d_out, int out_size) {
    const float* x    = (const float*)d_in[0];   // [16384, 4096]
    const float* v    = (const float*)d_in[1];   // [4096, 1]
    const float* bias = (const float*)d_in[2];   // [4096]
    float* out = (float*)d_out;

    const int n_rows = in_sizes[0] / N_COLS;     // 16384

    norm_kernel<<<1, 256>>>(v);
    householder_kernel<<<n_rows, TPB>>>(x, v, bias, out);
}

// round 2
// speedup vs baseline: 1.0351x; 1.0351x over previous
#include <cuda_runtime.h>
#include <math.h>

#define N_COLS 4096
#define TPB    256
#define EPS    1e-14f

// Fully fused: each block loads the whole of v anyway (L2/L1-resident 16KB),
// so it computes ||v||^2 locally alongside the row dot product.
// out[i] = x[i] - (2 * (x.v) / (||v||+eps)^2) * v[i] + bias[i]
__global__ void __launch_bounds__(TPB, 4)
householder_kernel(const float* __restrict__ x,
                   const float* __restrict__ v,
                   const float* __restrict__ bias,
                   float* __restrict__ out) {
    const int row = blockIdx.x;
    const float4* __restrict__ xr = (const float4*)(x + (size_t)row * N_COLS);
    const float4* __restrict__ vr = (const float4*)v;
    const float4* __restrict__ br = (const float4*)bias;
    float4* __restrict__       orow = (float4*)(out + (size_t)row * N_COLS);

    // 256 threads * 4 float4 = 4096 floats = one row; x, v in registers.
    float4 xv[4], vv[4];
    float dot = 0.0f;
    float vn  = 0.0f;
    #pragma unroll
    for (int j = 0; j < 4; j++) {
        int idx = threadIdx.x + j * TPB;   // coalesced 128B per warp
        xv[j] = __ldcs(&xr[idx]);          // streaming: no L2 reuse for x
        vv[j] = vr[idx];                   // cached: v is hot in L2/L1
        dot = fmaf(xv[j].x, vv[j].x, dot);
        dot = fmaf(xv[j].y, vv[j].y, dot);
        dot = fmaf(xv[j].z, vv[j].z, dot);
        dot = fmaf(xv[j].w, vv[j].w, dot);
        vn  = fmaf(vv[j].x, vv[j].x, vn);
        vn  = fmaf(vv[j].y, vv[j].y, vn);
        vn  = fmaf(vv[j].z, vv[j].z, vn);
        vn  = fmaf(vv[j].w, vv[j].w, vn);
    }

    // block reduction of (dot, vnorm2)
    #pragma unroll
    for (int o = 16; o > 0; o >>= 1) {
        dot += __shfl_xor_sync(0xffffffffu, dot, o);
        vn  += __shfl_xor_sync(0xffffffffu, vn,  o);
    }

    __shared__ float red_d[TPB / 32];
    __shared__ float red_n[TPB / 32];
    __shared__ float coef_sh;
    int w = threadIdx.x >> 5, l = threadIdx.x & 31;
    if (l == 0) { red_d[w] = dot; red_n[w] = vn; }
    __syncthreads();
    if (threadIdx.x == 0) {
        float td = 0.0f, tn = 0.0f;
        #pragma unroll
        for (int i = 0; i < TPB / 32; i++) { td += red_d[i]; tn += red_n[i]; }
        float s = 1.0f / (sqrtf(tn) + EPS);
        coef_sh = 2.0f * td * s * s;
    }
    __syncthreads();
    const float coef = coef_sh;

    #pragma unroll
    for (int j = 0; j < 4; j++) {
        int idx = threadIdx.x + j * TPB;
        float4 bb = br[idx];
        float4 o4;
        o4.x = fmaf(-coef, vv[j].x, xv[j].x) + bb.x;
        o4.y = fmaf(-coef, vv[j].y, xv[j].y) + bb.y;
        o4.z = fmaf(-coef, vv[j].z, xv[j].z) + bb.z;
        o4.w = fmaf(-coef, vv[j].w, xv[j].w) + bb.w;
        __stcs(&orow[idx], o4);            // streaming store: out not re-read
    }
}

extern "C" void kernel_launch(void* const* d_in, const int* in_sizes, int n_in,
                              void* d_out, int out_size) {
    const float* x    = (const float*)d_in[0];   // [16384, 4096]
    const float* v    = (const float*)d_in[1];   // [4096, 1]
    const float* bias = (const float*)d_in[2];   // [4096]
    float* out = (float*)d_out;

    const int n_rows = in_sizes[0] / N_COLS;     // 16384

    householder_kernel<<<n_rows, TPB>>>(x, v, bias, out);
}